// round 14
// baseline (speedup 1.0000x reference)
#include <cuda_runtime.h>
#include <cuda_fp16.h>
#include <math.h>
#include <stdint.h>

// Problem constants
#define BB    8
#define LL    4096
#define HH    512
#define PP    512
#define MM    (BB*LL)     // 32768 tokens
#define N1    (2*PP)      // 1024  (Bu_re | Bu_im)
#define K1    HH          // 512
#define N2    HH          // 512
#define K2    (2*PP)      // 1024  (x_re | x_im)
#define NCHUNK 64
#define CLEN   64         // LL / NCHUNK

// ---------------- static device scratch -------------------------------------
__device__ __half  d_Bu [(size_t)MM * N1];   // Bu fp16 (64MB)
__device__ __half  d_Uh [(size_t)MM * K1];   // u rounded to fp16 (32MB)
__device__ __half  d_Xh [(size_t)MM * K2];   // xs rounded to fp16 (64MB)
__device__ __half  d_W1 [N1 * K1];           // B_bar folded, fp16
__device__ __half  d_W2 [N2 * K2];           // [2C_re | -2C_im], fp16
__device__ float2 d_Lam[PP];
__device__ float2 d_LamPow[PP];              // lam^CLEN
__device__ float2 d_yend[BB * NCHUNK * PP];
__device__ float2 d_cin [BB * NCHUNK * PP];

// ---------------- helpers ----------------------------------------------------
__device__ __forceinline__ uint32_t smem_u32(const void* p) {
    uint32_t a;
    asm("{ .reg .u64 t; cvta.to.shared.u64 t, %1; cvt.u32.u64 %0, t; }" : "=r"(a) : "l"(p));
    return a;
}
__device__ __forceinline__ void cp16(uint32_t saddr, const void* g) {
    asm volatile("cp.async.cg.shared.global [%0], [%1], 16;" :: "r"(saddr), "l"(g));
}
#define CP_COMMIT() asm volatile("cp.async.commit_group;" ::: "memory")
#define CP_WAIT(n)  asm volatile("cp.async.wait_group %0;" :: "n"(n) : "memory")

__device__ __forceinline__ void ldm_x4(uint32_t addr, uint32_t* r) {
    asm volatile("ldmatrix.sync.aligned.m8n8.x4.shared.b16 {%0,%1,%2,%3}, [%4];"
                 : "=r"(r[0]), "=r"(r[1]), "=r"(r[2]), "=r"(r[3]) : "r"(addr));
}
__device__ __forceinline__ void hmma(float* c, const uint32_t* a, const uint32_t* b) {
    asm volatile(
        "mma.sync.aligned.m16n8k16.row.col.f32.f16.f16.f32 "
        "{%0,%1,%2,%3}, {%4,%5,%6,%7}, {%8,%9}, {%0,%1,%2,%3};"
        : "+f"(c[0]), "+f"(c[1]), "+f"(c[2]), "+f"(c[3])
        : "r"(a[0]), "r"(a[1]), "r"(a[2]), "r"(a[3]), "r"(b[0]), "r"(b[1]));
}

// XOR swizzle inside a 128-row x 64B tile: (row, c16 in 0..3) -> byte offset
__device__ __forceinline__ uint32_t sw_off(int row, int c16) {
    return (uint32_t)(row * 64 + ((c16 ^ ((row >> 1) & 3)) << 4));
}

// ---------------- setup: discretize in fp64, build W1 and W2 (merged) --------
__global__ void setup_kernel(const float* __restrict__ Lre, const float* __restrict__ Lim,
                             const float* __restrict__ Bre, const float* __restrict__ Bim,
                             const float* __restrict__ Cre, const float* __restrict__ Cim,
                             const float* __restrict__ log_step) {
    if (blockIdx.x >= PP) {
        // W2 part: blocks PP .. PP + (HH*PP/256) - 1
        int idx = (blockIdx.x - PP) * blockDim.x + threadIdx.x;
        int h = idx >> 9, p = idx & (PP - 1);
        d_W2[h * K2 + p]      = __float2half( 2.0f * Cre[h * PP + p]);
        d_W2[h * K2 + PP + p] = __float2half(-2.0f * Cim[h * PP + p]);
        return;
    }
    int p = blockIdx.x;
    __shared__ float2 s_f;
    if (threadIdx.x == 0) {
        double lr = (double)Lre[p], li = (double)Lim[p];
        double dt = exp((double)log_step[p]);
        double mag = exp(lr * dt);
        double lam_r = mag * cos(li * dt);
        double lam_i = mag * sin(li * dt);
        d_Lam[p] = make_float2((float)lam_r, (float)lam_i);
        double nr = lam_r - 1.0, ni = lam_i;
        double den = lr * lr + li * li;
        s_f = make_float2((float)((nr * lr + ni * li) / den),
                          (float)((ni * lr - nr * li) / den));
        // lam^64 via 6 squarings (double)
        double pr = lam_r, pi = lam_i;
        #pragma unroll
        for (int i = 0; i < 6; i++) { double r2 = pr*pr - pi*pi, i2 = 2.0*pr*pi; pr = r2; pi = i2; }
        d_LamPow[p] = make_float2((float)pr, (float)pi);
    }
    __syncthreads();
    float fr = s_f.x, fi = s_f.y;
    for (int h = threadIdx.x; h < HH; h += blockDim.x) {
        float br = Bre[p * HH + h], bi = Bim[p * HH + h];
        d_W1[p * K1 + h]        = __float2half(fr * br - fi * bi);   // Re(B_bar)
        d_W1[(PP + p) * K1 + h] = __float2half(fr * bi + fi * br);   // Im(B_bar)
    }
}

// vectorized: 8 floats -> 8 halves (one uint4 store) per thread
__global__ void uconv_kernel(const float* __restrict__ u) {
    size_t i = ((size_t)blockIdx.x * blockDim.x + threadIdx.x) * 8;
    float4 a = *(const float4*)(u + i);
    float4 b = *(const float4*)(u + i + 4);
    __half2 h0 = __floats2half2_rn(a.x, a.y);
    __half2 h1 = __floats2half2_rn(a.z, a.w);
    __half2 h2 = __floats2half2_rn(b.x, b.y);
    __half2 h3 = __floats2half2_rn(b.z, b.w);
    uint4 out;
    out.x = *(uint32_t*)&h0; out.y = *(uint32_t*)&h1;
    out.z = *(uint32_t*)&h2; out.w = *(uint32_t*)&h3;
    *(uint4*)(d_Uh + i) = out;
}

// ---------------- HMMA fp16 GEMM: C[m,n] = sum_k A[m,k]*W[n,k] ---------------
// 128x128 CTA tile, BK=32, 4 warps of 64x64 (128 threads).
// 5-stage cp.async pipeline, 64B-row XOR-swizzled tiles, 1 barrier/chunk.
#define TILE_B  (128 * 64)               // 8192 B
#define STAGE_B (2 * TILE_B)             // A, W = 16384 B
#define NSTAGE  5
#define GSMEM   (NSTAGE * STAGE_B)       // 81920 B

template <int OUT_HALF>
__global__ void __launch_bounds__(128, 2)
hmma_gemm(const __half* __restrict__ A, const __half* __restrict__ W,
          void* __restrict__ Cv, int N, int K) {
    extern __shared__ char smem[];
    const uint32_t sb = smem_u32(smem);
    const int tid = threadIdx.x;
    const int wid = tid >> 5, lane = tid & 31;
    const int wm = wid >> 1, wn = wid & 1;       // warp tile: rows wm*64, cols wn*64
    const int m0 = blockIdx.y * 128, n0 = blockIdx.x * 128;

    const char* srcs[2] = {
        (const char*)(A + (size_t)m0 * K),
        (const char*)(W + (size_t)n0 * K) };
    const size_t rstride = (size_t)K * 2;

    auto prefetch = [&](int stage, int ci) {
        #pragma unroll
        for (int it = 0; it < 8; it++) {
            int id = it * 128 + tid;            // 0..1023
            int t = id >> 9;                    // tile 0..1
            int w = id & 511;
            int row = w >> 2, c = w & 3;
            cp16(sb + stage * STAGE_B + t * TILE_B + sw_off(row, c),
                 srcs[t] + (size_t)ci * 64 + (size_t)row * rstride + c * 16);
        }
    };

    float acc[4][8][4];
    #pragma unroll
    for (int i = 0; i < 4; i++)
        #pragma unroll
        for (int j = 0; j < 8; j++)
            #pragma unroll
            for (int q = 0; q < 4; q++) acc[i][j][q] = 0.f;

    const int nch = K / 32;
    prefetch(0, 0); CP_COMMIT();
    prefetch(1, 1); CP_COMMIT();
    prefetch(2, 2); CP_COMMIT();
    prefetch(3, 3); CP_COMMIT();

    // fragment address components (per lane)
    const int a_row = lane & 15;
    const int a_c   = lane >> 4;                  // +0 or +1 16B column
    const int b_row = (lane & 7) + ((lane >> 4) & 1) * 8;
    const int b_c   = (lane >> 3) & 1;

    int s = 0;
    for (int ci = 0; ci < nch; ci++) {
        CP_WAIT(3);
        __syncthreads();

        uint32_t sA = sb + s * STAGE_B + 0 * TILE_B;
        uint32_t sW = sb + s * STAGE_B + 1 * TILE_B;

        #pragma unroll
        for (int ks = 0; ks < 2; ks++) {
            // B fragments up front
            uint32_t bw[8][2];
            #pragma unroll
            for (int np = 0; np < 4; np++) {
                int brow = wn * 64 + np * 16 + b_row;
                uint32_t r[4];
                ldm_x4(sW + sw_off(brow, ks * 2 + b_c), r);
                bw[np*2][0] = r[0]; bw[np*2][1] = r[1];
                bw[np*2+1][0] = r[2]; bw[np*2+1][1] = r[3];
            }
            // A-fragment lookahead: double-buffered in registers
            uint32_t av[2][4];
            ldm_x4(sA + sw_off(wm * 64 + a_row, ks * 2 + a_c), av[0]);
            #pragma unroll
            for (int mt = 0; mt < 4; mt++) {
                if (mt < 3) {
                    int arow = wm * 64 + (mt + 1) * 16 + a_row;
                    ldm_x4(sA + sw_off(arow, ks * 2 + a_c), av[(mt + 1) & 1]);
                }
                #pragma unroll
                for (int nt = 0; nt < 8; nt++) hmma(acc[mt][nt], av[mt & 1], bw[nt]);
            }
        }
        // prefetch 4 chunks ahead into the stage freed last iteration
        if (ci + 4 < nch) prefetch((s + 4) % NSTAGE, ci + 4);
        CP_COMMIT();
        s = (s + 1 == NSTAGE) ? 0 : s + 1;
    }

    // epilogue
    #pragma unroll
    for (int mt = 0; mt < 4; mt++) {
        int r = m0 + wm * 64 + mt * 16 + (lane >> 2);
        #pragma unroll
        for (int nt = 0; nt < 8; nt++) {
            int c = n0 + wn * 64 + nt * 8 + (lane & 3) * 2;
            if (OUT_HALF) {
                __half* C = (__half*)Cv;
                *(__half2*)(C + (size_t)r * N + c) =
                    __floats2half2_rn(acc[mt][nt][0], acc[mt][nt][1]);
                *(__half2*)(C + (size_t)(r + 8) * N + c) =
                    __floats2half2_rn(acc[mt][nt][2], acc[mt][nt][3]);
            } else {
                float* C = (float*)Cv;
                *(float2*)(C + (size_t)r * N + c)       = make_float2(acc[mt][nt][0], acc[mt][nt][1]);
                *(float2*)(C + (size_t)(r + 8) * N + c) = make_float2(acc[mt][nt][2], acc[mt][nt][3]);
            }
        }
    }
}

// ---------------- chunked complex scan over L (Bu fp16, 4 p's per thread) ----
__global__ void scan_phaseA() {
    int idx = blockIdx.x * blockDim.x + threadIdx.x;
    int pv = idx & 127;                  // 4-half group; p0 = 4*pv
    int c  = (idx >> 7) & (NCHUNK - 1);
    int b  = idx >> 13;
    float2 lam[4];
    float xr[4], xi[4];
    #pragma unroll
    for (int q = 0; q < 4; q++) { lam[q] = d_Lam[4 * pv + q]; xr[q] = 0.f; xi[q] = 0.f; }
    size_t base = ((size_t)b * LL + (size_t)c * CLEN) * N1;
    const uint2* Xr = (const uint2*)(d_Bu + base) + pv;
    const uint2* Xi = (const uint2*)(d_Bu + base + PP) + pv;
    #pragma unroll 4
    for (int j = 0; j < CLEN; j++) {
        uint2 vr = Xr[(size_t)j * (N1 / 4)];
        uint2 vi = Xi[(size_t)j * (N1 / 4)];
        float2 br01 = __half22float2(*(__half2*)&vr.x);
        float2 br23 = __half22float2(*(__half2*)&vr.y);
        float2 bi01 = __half22float2(*(__half2*)&vi.x);
        float2 bi23 = __half22float2(*(__half2*)&vi.y);
        float br[4] = {br01.x, br01.y, br23.x, br23.y};
        float bi[4] = {bi01.x, bi01.y, bi23.x, bi23.y};
        #pragma unroll
        for (int q = 0; q < 4; q++) {
            float nr = fmaf(lam[q].x, xr[q], fmaf(-lam[q].y, xi[q], br[q]));
            float ni = fmaf(lam[q].x, xi[q], fmaf( lam[q].y, xr[q], bi[q]));
            xr[q] = nr; xi[q] = ni;
        }
    }
    int yb = (b * NCHUNK + c) * PP + 4 * pv;
    #pragma unroll
    for (int q = 0; q < 4; q++) d_yend[yb + q] = make_float2(xr[q], xi[q]);
}

__global__ void scan_phaseB() {
    int idx = blockIdx.x * blockDim.x + threadIdx.x;
    int p = idx & (PP - 1);
    int b = idx >> 9;
    float2 pw = d_LamPow[p];
    float cr = 0.f, ci = 0.f;
    #pragma unroll
    for (int c = 0; c < NCHUNK; c++) {
        d_cin[(b * NCHUNK + c) * PP + p] = make_float2(cr, ci);
        float2 ye = d_yend[(b * NCHUNK + c) * PP + p];
        float nr = fmaf(pw.x, cr, fmaf(-pw.y, ci, ye.x));
        float ni = fmaf(pw.x, ci, fmaf( pw.y, cr, ye.y));
        cr = nr; ci = ni;
    }
}

// phaseC: apply carry-in, emit xs rounded to fp16 for GEMM2
__global__ void scan_phaseC() {
    int idx = blockIdx.x * blockDim.x + threadIdx.x;
    int pv = idx & 127;
    int c  = (idx >> 7) & (NCHUNK - 1);
    int b  = idx >> 13;
    float2 lam[4];
    float xr[4], xi[4];
    int cb = (b * NCHUNK + c) * PP + 4 * pv;
    #pragma unroll
    for (int q = 0; q < 4; q++) {
        lam[q] = d_Lam[4 * pv + q];
        float2 c0 = d_cin[cb + q];
        xr[q] = c0.x; xi[q] = c0.y;
    }
    size_t mrow = (size_t)b * LL + (size_t)c * CLEN;
    const uint2* Xr = (const uint2*)(d_Bu + mrow * N1) + pv;
    const uint2* Xi = (const uint2*)(d_Bu + mrow * N1 + PP) + pv;
    uint2* Hr = (uint2*)(d_Xh + mrow * K2) + pv;
    uint2* Hi = (uint2*)(d_Xh + mrow * K2 + PP) + pv;
    #pragma unroll 4
    for (int j = 0; j < CLEN; j++) {
        uint2 vr = Xr[(size_t)j * (N1 / 4)];
        uint2 vi = Xi[(size_t)j * (N1 / 4)];
        float2 br01 = __half22float2(*(__half2*)&vr.x);
        float2 br23 = __half22float2(*(__half2*)&vr.y);
        float2 bi01 = __half22float2(*(__half2*)&vi.x);
        float2 bi23 = __half22float2(*(__half2*)&vi.y);
        float br[4] = {br01.x, br01.y, br23.x, br23.y};
        float bi[4] = {bi01.x, bi01.y, bi23.x, bi23.y};
        #pragma unroll
        for (int q = 0; q < 4; q++) {
            float nr = fmaf(lam[q].x, xr[q], fmaf(-lam[q].y, xi[q], br[q]));
            float ni = fmaf(lam[q].x, xi[q], fmaf( lam[q].y, xr[q], bi[q]));
            xr[q] = nr; xi[q] = ni;
        }
        __half2 hr01 = __floats2half2_rn(xr[0], xr[1]);
        __half2 hr23 = __floats2half2_rn(xr[2], xr[3]);
        __half2 hi01 = __floats2half2_rn(xi[0], xi[1]);
        __half2 hi23 = __floats2half2_rn(xi[2], xi[3]);
        uint2 wr, wi;
        wr.x = *(uint32_t*)&hr01; wr.y = *(uint32_t*)&hr23;
        wi.x = *(uint32_t*)&hi01; wi.y = *(uint32_t*)&hi23;
        Hr[(size_t)j * (K2 / 4)] = wr;
        Hi[(size_t)j * (K2 / 4)] = wi;
    }
}

// ---------------- launch -----------------------------------------------------
extern "C" void kernel_launch(void* const* d_in, const int* in_sizes, int n_in,
                              void* d_out, int out_size) {
    const float* Lre      = (const float*)d_in[0];
    const float* Lim      = (const float*)d_in[1];
    const float* Bre      = (const float*)d_in[2];
    const float* Bim      = (const float*)d_in[3];
    const float* Cre      = (const float*)d_in[4];
    const float* Cim      = (const float*)d_in[5];
    const float* log_step = (const float*)d_in[6];
    const float* u        = (const float*)d_in[7];
    float* out = (float*)d_out;

    __half *Bu, *Uh, *Xh, *W1p, *W2p;
    cudaGetSymbolAddress((void**)&Bu,  d_Bu);
    cudaGetSymbolAddress((void**)&Uh,  d_Uh);
    cudaGetSymbolAddress((void**)&Xh,  d_Xh);
    cudaGetSymbolAddress((void**)&W1p, d_W1);
    cudaGetSymbolAddress((void**)&W2p, d_W2);

    cudaFuncSetAttribute(hmma_gemm<1>, cudaFuncAttributeMaxDynamicSharedMemorySize, GSMEM);
    cudaFuncSetAttribute(hmma_gemm<0>, cudaFuncAttributeMaxDynamicSharedMemorySize, GSMEM);

    // merged setup: blocks [0, PP) build W1/Lam/LamPow; blocks [PP, PP+1024) build W2
    setup_kernel<<<PP + (HH * PP) / 256, 256>>>(Lre, Lim, Bre, Bim, Cre, Cim, log_step);
    uconv_kernel<<<(int)(((size_t)MM * K1) / 8 / 256), 256>>>(u);

    // GEMM1: Bu(re|im) = u @ W1^T -> d_Bu fp16 (M x 1024)
    hmma_gemm<1><<<dim3(N1 / 128, MM / 128), 128, GSMEM>>>(Uh, W1p, Bu, N1, K1);

    // chunked complex scan; phaseC emits fp16 xs
    scan_phaseA<<<(BB * NCHUNK * PP / 4) / 256, 256>>>();
    scan_phaseB<<<(BB * PP) / 256, 256>>>();
    scan_phaseC<<<(BB * NCHUNK * PP / 4) / 256, 256>>>();

    // GEMM2: ys = xs @ W2^T -> out fp32 (M x 512)
    hmma_gemm<0><<<dim3(N2 / 128, MM / 128), 128, GSMEM>>>(Xh, W2p, out, N2, K2);
}

// round 15
// speedup vs baseline: 1.0320x; 1.0320x over previous
#include <cuda_runtime.h>
#include <cuda_fp16.h>
#include <math.h>
#include <stdint.h>

// Problem constants
#define BB    8
#define LL    4096
#define HH    512
#define PP    512
#define MM    (BB*LL)     // 32768 tokens
#define N1    (2*PP)      // 1024  (Bu_re | Bu_im)
#define K1    HH          // 512
#define N2    HH          // 512
#define K2    (2*PP)      // 1024  (x_re | x_im)
#define NCHUNK 128
#define CLEN   32         // LL / NCHUNK

// ---------------- static device scratch -------------------------------------
__device__ __half  d_Bu [(size_t)MM * N1];   // Bu fp16 (64MB)
__device__ __half  d_Uh [(size_t)MM * K1];   // u rounded to fp16 (32MB)
__device__ __half  d_Xh [(size_t)MM * K2];   // xs rounded to fp16 (64MB)
__device__ __half  d_W1 [N1 * K1];           // B_bar folded, fp16
__device__ __half  d_W2 [N2 * K2];           // [2C_re | -2C_im], fp16
__device__ float2 d_Lam[PP];
__device__ float2 d_LamPow[PP];              // lam^CLEN
__device__ float2 d_yend[BB * NCHUNK * PP];
__device__ float2 d_cin [BB * NCHUNK * PP];

// ---------------- helpers ----------------------------------------------------
__device__ __forceinline__ uint32_t smem_u32(const void* p) {
    uint32_t a;
    asm("{ .reg .u64 t; cvta.to.shared.u64 t, %1; cvt.u32.u64 %0, t; }" : "=r"(a) : "l"(p));
    return a;
}
__device__ __forceinline__ void cp16(uint32_t saddr, const void* g) {
    asm volatile("cp.async.cg.shared.global [%0], [%1], 16;" :: "r"(saddr), "l"(g));
}
#define CP_COMMIT() asm volatile("cp.async.commit_group;" ::: "memory")
#define CP_WAIT(n)  asm volatile("cp.async.wait_group %0;" :: "n"(n) : "memory")

__device__ __forceinline__ void ldm_x4(uint32_t addr, uint32_t* r) {
    asm volatile("ldmatrix.sync.aligned.m8n8.x4.shared.b16 {%0,%1,%2,%3}, [%4];"
                 : "=r"(r[0]), "=r"(r[1]), "=r"(r[2]), "=r"(r[3]) : "r"(addr));
}
__device__ __forceinline__ void hmma(float* c, const uint32_t* a, const uint32_t* b) {
    asm volatile(
        "mma.sync.aligned.m16n8k16.row.col.f32.f16.f16.f32 "
        "{%0,%1,%2,%3}, {%4,%5,%6,%7}, {%8,%9}, {%0,%1,%2,%3};"
        : "+f"(c[0]), "+f"(c[1]), "+f"(c[2]), "+f"(c[3])
        : "r"(a[0]), "r"(a[1]), "r"(a[2]), "r"(a[3]), "r"(b[0]), "r"(b[1]));
}

// XOR swizzle inside a 128-row x 64B tile: (row, c16 in 0..3) -> byte offset
__device__ __forceinline__ uint32_t sw_off(int row, int c16) {
    return (uint32_t)(row * 64 + ((c16 ^ ((row >> 1) & 3)) << 4));
}

// ---------------- setup: discretize in fp64, build W1 and W2 (merged) --------
__global__ void setup_kernel(const float* __restrict__ Lre, const float* __restrict__ Lim,
                             const float* __restrict__ Bre, const float* __restrict__ Bim,
                             const float* __restrict__ Cre, const float* __restrict__ Cim,
                             const float* __restrict__ log_step) {
    if (blockIdx.x >= PP) {
        int idx = (blockIdx.x - PP) * blockDim.x + threadIdx.x;
        int h = idx >> 9, p = idx & (PP - 1);
        d_W2[h * K2 + p]      = __float2half( 2.0f * Cre[h * PP + p]);
        d_W2[h * K2 + PP + p] = __float2half(-2.0f * Cim[h * PP + p]);
        return;
    }
    int p = blockIdx.x;
    __shared__ float2 s_f;
    if (threadIdx.x == 0) {
        double lr = (double)Lre[p], li = (double)Lim[p];
        double dt = exp((double)log_step[p]);
        double mag = exp(lr * dt);
        double lam_r = mag * cos(li * dt);
        double lam_i = mag * sin(li * dt);
        d_Lam[p] = make_float2((float)lam_r, (float)lam_i);
        double nr = lam_r - 1.0, ni = lam_i;
        double den = lr * lr + li * li;
        s_f = make_float2((float)((nr * lr + ni * li) / den),
                          (float)((ni * lr - nr * li) / den));
        // lam^32 via 5 squarings (double)
        double pr = lam_r, pi = lam_i;
        #pragma unroll
        for (int i = 0; i < 5; i++) { double r2 = pr*pr - pi*pi, i2 = 2.0*pr*pi; pr = r2; pi = i2; }
        d_LamPow[p] = make_float2((float)pr, (float)pi);
    }
    __syncthreads();
    float fr = s_f.x, fi = s_f.y;
    for (int h = threadIdx.x; h < HH; h += blockDim.x) {
        float br = Bre[p * HH + h], bi = Bim[p * HH + h];
        d_W1[p * K1 + h]        = __float2half(fr * br - fi * bi);   // Re(B_bar)
        d_W1[(PP + p) * K1 + h] = __float2half(fr * bi + fi * br);   // Im(B_bar)
    }
}

// vectorized: 8 floats -> 8 halves (one uint4 store) per thread
__global__ void uconv_kernel(const float* __restrict__ u) {
    size_t i = ((size_t)blockIdx.x * blockDim.x + threadIdx.x) * 8;
    float4 a = *(const float4*)(u + i);
    float4 b = *(const float4*)(u + i + 4);
    __half2 h0 = __floats2half2_rn(a.x, a.y);
    __half2 h1 = __floats2half2_rn(a.z, a.w);
    __half2 h2 = __floats2half2_rn(b.x, b.y);
    __half2 h3 = __floats2half2_rn(b.z, b.w);
    uint4 out;
    out.x = *(uint32_t*)&h0; out.y = *(uint32_t*)&h1;
    out.z = *(uint32_t*)&h2; out.w = *(uint32_t*)&h3;
    *(uint4*)(d_Uh + i) = out;
}

// ---------------- HMMA fp16 GEMM: C[m,n] = sum_k A[m,k]*W[n,k] ---------------
// 128x128 CTA tile, BK=32, 4 warps of 64x64 (128 threads).
// 4-stage cp.async pipeline, 64B-row XOR-swizzled tiles, 1 barrier/chunk.
#define TILE_B  (128 * 64)               // 8192 B
#define STAGE_B (2 * TILE_B)             // A, W = 16384 B
#define NSTAGE  4
#define GSMEM   (NSTAGE * STAGE_B)       // 65536 B

template <int OUT_HALF>
__global__ void __launch_bounds__(128, 2)
hmma_gemm(const __half* __restrict__ A, const __half* __restrict__ W,
          void* __restrict__ Cv, int N, int K) {
    extern __shared__ char smem[];
    const uint32_t sb = smem_u32(smem);
    const int tid = threadIdx.x;
    const int wid = tid >> 5, lane = tid & 31;
    const int wm = wid >> 1, wn = wid & 1;       // warp tile: rows wm*64, cols wn*64
    const int m0 = blockIdx.y * 128, n0 = blockIdx.x * 128;

    const char* srcs[2] = {
        (const char*)(A + (size_t)m0 * K),
        (const char*)(W + (size_t)n0 * K) };
    const size_t rstride = (size_t)K * 2;

    auto prefetch = [&](int stage, int ci) {
        #pragma unroll
        for (int it = 0; it < 8; it++) {
            int id = it * 128 + tid;            // 0..1023
            int t = id >> 9;                    // tile 0..1
            int w = id & 511;
            int row = w >> 2, c = w & 3;
            cp16(sb + stage * STAGE_B + t * TILE_B + sw_off(row, c),
                 srcs[t] + (size_t)ci * 64 + (size_t)row * rstride + c * 16);
        }
    };

    float acc[4][8][4];
    #pragma unroll
    for (int i = 0; i < 4; i++)
        #pragma unroll
        for (int j = 0; j < 8; j++)
            #pragma unroll
            for (int q = 0; q < 4; q++) acc[i][j][q] = 0.f;

    const int nch = K / 32;
    prefetch(0, 0); CP_COMMIT();
    prefetch(1, 1); CP_COMMIT();
    prefetch(2, 2); CP_COMMIT();

    // fragment address components (per lane)
    const int a_row = lane & 15;
    const int a_c   = lane >> 4;                  // +0 or +1 16B column
    const int b_row = (lane & 7) + ((lane >> 4) & 1) * 8;
    const int b_c   = (lane >> 3) & 1;

    int s = 0;
    for (int ci = 0; ci < nch; ci++) {
        CP_WAIT(2);
        __syncthreads();

        uint32_t sA = sb + s * STAGE_B + 0 * TILE_B;
        uint32_t sW = sb + s * STAGE_B + 1 * TILE_B;

        #pragma unroll
        for (int ks = 0; ks < 2; ks++) {
            // B fragments up front
            uint32_t bw[8][2];
            #pragma unroll
            for (int np = 0; np < 4; np++) {
                int brow = wn * 64 + np * 16 + b_row;
                uint32_t r[4];
                ldm_x4(sW + sw_off(brow, ks * 2 + b_c), r);
                bw[np*2][0] = r[0]; bw[np*2][1] = r[1];
                bw[np*2+1][0] = r[2]; bw[np*2+1][1] = r[3];
            }
            // A-fragment lookahead: double-buffered in registers
            uint32_t av[2][4];
            ldm_x4(sA + sw_off(wm * 64 + a_row, ks * 2 + a_c), av[0]);
            #pragma unroll
            for (int mt = 0; mt < 4; mt++) {
                if (mt < 3) {
                    int arow = wm * 64 + (mt + 1) * 16 + a_row;
                    ldm_x4(sA + sw_off(arow, ks * 2 + a_c), av[(mt + 1) & 1]);
                }
                #pragma unroll
                for (int nt = 0; nt < 8; nt++) hmma(acc[mt][nt], av[mt & 1], bw[nt]);
            }
        }
        // prefetch 3 chunks ahead into the stage freed by this iteration
        if (ci + 3 < nch) prefetch((s + 3) & 3, ci + 3);
        CP_COMMIT();
        s = (s + 1) & 3;
    }

    // epilogue
    #pragma unroll
    for (int mt = 0; mt < 4; mt++) {
        int r = m0 + wm * 64 + mt * 16 + (lane >> 2);
        #pragma unroll
        for (int nt = 0; nt < 8; nt++) {
            int c = n0 + wn * 64 + nt * 8 + (lane & 3) * 2;
            if (OUT_HALF) {
                __half* C = (__half*)Cv;
                *(__half2*)(C + (size_t)r * N + c) =
                    __floats2half2_rn(acc[mt][nt][0], acc[mt][nt][1]);
                *(__half2*)(C + (size_t)(r + 8) * N + c) =
                    __floats2half2_rn(acc[mt][nt][2], acc[mt][nt][3]);
            } else {
                float* C = (float*)Cv;
                *(float2*)(C + (size_t)r * N + c)       = make_float2(acc[mt][nt][0], acc[mt][nt][1]);
                *(float2*)(C + (size_t)(r + 8) * N + c) = make_float2(acc[mt][nt][2], acc[mt][nt][3]);
            }
        }
    }
}

// ---------------- chunked complex scan over L (Bu fp16, 4 p's per thread) ----
__global__ void scan_phaseA() {
    int idx = blockIdx.x * blockDim.x + threadIdx.x;
    int pv = idx & 127;                  // 4-half group; p0 = 4*pv
    int c  = (idx >> 7) & (NCHUNK - 1);
    int b  = idx >> 14;
    float2 lam[4];
    float xr[4], xi[4];
    #pragma unroll
    for (int q = 0; q < 4; q++) { lam[q] = d_Lam[4 * pv + q]; xr[q] = 0.f; xi[q] = 0.f; }
    size_t base = ((size_t)b * LL + (size_t)c * CLEN) * N1;
    const uint2* Xr = (const uint2*)(d_Bu + base) + pv;
    const uint2* Xi = (const uint2*)(d_Bu + base + PP) + pv;
    #pragma unroll 4
    for (int j = 0; j < CLEN; j++) {
        uint2 vr = Xr[(size_t)j * (N1 / 4)];
        uint2 vi = Xi[(size_t)j * (N1 / 4)];
        float2 br01 = __half22float2(*(__half2*)&vr.x);
        float2 br23 = __half22float2(*(__half2*)&vr.y);
        float2 bi01 = __half22float2(*(__half2*)&vi.x);
        float2 bi23 = __half22float2(*(__half2*)&vi.y);
        float br[4] = {br01.x, br01.y, br23.x, br23.y};
        float bi[4] = {bi01.x, bi01.y, bi23.x, bi23.y};
        #pragma unroll
        for (int q = 0; q < 4; q++) {
            float nr = fmaf(lam[q].x, xr[q], fmaf(-lam[q].y, xi[q], br[q]));
            float ni = fmaf(lam[q].x, xi[q], fmaf( lam[q].y, xr[q], bi[q]));
            xr[q] = nr; xi[q] = ni;
        }
    }
    int yb = (b * NCHUNK + c) * PP + 4 * pv;
    #pragma unroll
    for (int q = 0; q < 4; q++) d_yend[yb + q] = make_float2(xr[q], xi[q]);
}

__global__ void scan_phaseB() {
    int idx = blockIdx.x * blockDim.x + threadIdx.x;
    int p = idx & (PP - 1);
    int b = idx >> 9;
    float2 pw = d_LamPow[p];
    float cr = 0.f, ci = 0.f;
    #pragma unroll 8
    for (int c = 0; c < NCHUNK; c++) {
        d_cin[(b * NCHUNK + c) * PP + p] = make_float2(cr, ci);
        float2 ye = d_yend[(b * NCHUNK + c) * PP + p];
        float nr = fmaf(pw.x, cr, fmaf(-pw.y, ci, ye.x));
        float ni = fmaf(pw.x, ci, fmaf( pw.y, cr, ye.y));
        cr = nr; ci = ni;
    }
}

// phaseC: apply carry-in, emit xs rounded to fp16 for GEMM2
__global__ void scan_phaseC() {
    int idx = blockIdx.x * blockDim.x + threadIdx.x;
    int pv = idx & 127;
    int c  = (idx >> 7) & (NCHUNK - 1);
    int b  = idx >> 14;
    float2 lam[4];
    float xr[4], xi[4];
    int cb = (b * NCHUNK + c) * PP + 4 * pv;
    #pragma unroll
    for (int q = 0; q < 4; q++) {
        lam[q] = d_Lam[4 * pv + q];
        float2 c0 = d_cin[cb + q];
        xr[q] = c0.x; xi[q] = c0.y;
    }
    size_t mrow = (size_t)b * LL + (size_t)c * CLEN;
    const uint2* Xr = (const uint2*)(d_Bu + mrow * N1) + pv;
    const uint2* Xi = (const uint2*)(d_Bu + mrow * N1 + PP) + pv;
    uint2* Hr = (uint2*)(d_Xh + mrow * K2) + pv;
    uint2* Hi = (uint2*)(d_Xh + mrow * K2 + PP) + pv;
    #pragma unroll 4
    for (int j = 0; j < CLEN; j++) {
        uint2 vr = Xr[(size_t)j * (N1 / 4)];
        uint2 vi = Xi[(size_t)j * (N1 / 4)];
        float2 br01 = __half22float2(*(__half2*)&vr.x);
        float2 br23 = __half22float2(*(__half2*)&vr.y);
        float2 bi01 = __half22float2(*(__half2*)&vi.x);
        float2 bi23 = __half22float2(*(__half2*)&vi.y);
        float br[4] = {br01.x, br01.y, br23.x, br23.y};
        float bi[4] = {bi01.x, bi01.y, bi23.x, bi23.y};
        #pragma unroll
        for (int q = 0; q < 4; q++) {
            float nr = fmaf(lam[q].x, xr[q], fmaf(-lam[q].y, xi[q], br[q]));
            float ni = fmaf(lam[q].x, xi[q], fmaf( lam[q].y, xr[q], bi[q]));
            xr[q] = nr; xi[q] = ni;
        }
        __half2 hr01 = __floats2half2_rn(xr[0], xr[1]);
        __half2 hr23 = __floats2half2_rn(xr[2], xr[3]);
        __half2 hi01 = __floats2half2_rn(xi[0], xi[1]);
        __half2 hi23 = __floats2half2_rn(xi[2], xi[3]);
        uint2 wr, wi;
        wr.x = *(uint32_t*)&hr01; wr.y = *(uint32_t*)&hr23;
        wi.x = *(uint32_t*)&hi01; wi.y = *(uint32_t*)&hi23;
        Hr[(size_t)j * (K2 / 4)] = wr;
        Hi[(size_t)j * (K2 / 4)] = wi;
    }
}

// ---------------- launch -----------------------------------------------------
extern "C" void kernel_launch(void* const* d_in, const int* in_sizes, int n_in,
                              void* d_out, int out_size) {
    const float* Lre      = (const float*)d_in[0];
    const float* Lim      = (const float*)d_in[1];
    const float* Bre      = (const float*)d_in[2];
    const float* Bim      = (const float*)d_in[3];
    const float* Cre      = (const float*)d_in[4];
    const float* Cim      = (const float*)d_in[5];
    const float* log_step = (const float*)d_in[6];
    const float* u        = (const float*)d_in[7];
    float* out = (float*)d_out;

    __half *Bu, *Uh, *Xh, *W1p, *W2p;
    cudaGetSymbolAddress((void**)&Bu,  d_Bu);
    cudaGetSymbolAddress((void**)&Uh,  d_Uh);
    cudaGetSymbolAddress((void**)&Xh,  d_Xh);
    cudaGetSymbolAddress((void**)&W1p, d_W1);
    cudaGetSymbolAddress((void**)&W2p, d_W2);

    cudaFuncSetAttribute(hmma_gemm<1>, cudaFuncAttributeMaxDynamicSharedMemorySize, GSMEM);
    cudaFuncSetAttribute(hmma_gemm<0>, cudaFuncAttributeMaxDynamicSharedMemorySize, GSMEM);

    // merged setup: blocks [0, PP) build W1/Lam/LamPow; blocks [PP, PP+1024) build W2
    setup_kernel<<<PP + (HH * PP) / 256, 256>>>(Lre, Lim, Bre, Bim, Cre, Cim, log_step);
    uconv_kernel<<<(int)(((size_t)MM * K1) / 8 / 256), 256>>>(u);

    // GEMM1: Bu(re|im) = u @ W1^T -> d_Bu fp16 (M x 1024)
    hmma_gemm<1><<<dim3(N1 / 128, MM / 128), 128, GSMEM>>>(Uh, W1p, Bu, N1, K1);

    // chunked complex scan; phaseC emits fp16 xs
    scan_phaseA<<<(BB * NCHUNK * PP / 4) / 256, 256>>>();
    scan_phaseB<<<(BB * PP) / 256, 256>>>();
    scan_phaseC<<<(BB * NCHUNK * PP / 4) / 256, 256>>>();

    // GEMM2: ys = xs @ W2^T -> out fp32 (M x 512)
    hmma_gemm<0><<<dim3(N2 / 128, MM / 128), 128, GSMEM>>>(Xh, W2p, out, N2, K2);
}

// round 16
// speedup vs baseline: 1.1892x; 1.1523x over previous
#include <cuda_runtime.h>
#include <cuda_fp16.h>
#include <math.h>
#include <stdint.h>

// Problem constants
#define BB    8
#define BH    4           // batches per half-pipeline
#define LL    4096
#define HH    512
#define PP    512
#define MM    (BB*LL)     // 32768 tokens
#define MH    (BH*LL)     // 16384 tokens per half
#define N1    (2*PP)      // 1024  (Bu_re | Bu_im)
#define K1    HH          // 512
#define N2    HH          // 512
#define K2    (2*PP)      // 1024  (x_re | x_im)
#define NCHUNK 128
#define CLEN   32         // LL / NCHUNK

// ---------------- static device scratch -------------------------------------
__device__ __half  d_Bu [(size_t)MM * N1];   // Bu fp16 (64MB)
__device__ __half  d_Uh [(size_t)MM * K1];   // u rounded to fp16 (32MB)
__device__ __half  d_Xh [(size_t)MM * K2];   // xs rounded to fp16 (64MB)
__device__ __half  d_W1 [N1 * K1];           // B_bar folded, fp16
__device__ __half  d_W2 [N2 * K2];           // [2C_re | -2C_im], fp16
__device__ float2 d_Lam[PP];
__device__ float2 d_LamPow[PP];              // lam^CLEN
__device__ float2 d_yend[BB * NCHUNK * PP];
__device__ float2 d_cin [BB * NCHUNK * PP];

// ---------------- helpers ----------------------------------------------------
__device__ __forceinline__ uint32_t smem_u32(const void* p) {
    uint32_t a;
    asm("{ .reg .u64 t; cvta.to.shared.u64 t, %1; cvt.u32.u64 %0, t; }" : "=r"(a) : "l"(p));
    return a;
}
__device__ __forceinline__ void cp16(uint32_t saddr, const void* g) {
    asm volatile("cp.async.cg.shared.global [%0], [%1], 16;" :: "r"(saddr), "l"(g));
}
#define CP_COMMIT() asm volatile("cp.async.commit_group;" ::: "memory")
#define CP_WAIT(n)  asm volatile("cp.async.wait_group %0;" :: "n"(n) : "memory")

__device__ __forceinline__ void ldm_x4(uint32_t addr, uint32_t* r) {
    asm volatile("ldmatrix.sync.aligned.m8n8.x4.shared.b16 {%0,%1,%2,%3}, [%4];"
                 : "=r"(r[0]), "=r"(r[1]), "=r"(r[2]), "=r"(r[3]) : "r"(addr));
}
__device__ __forceinline__ void hmma(float* c, const uint32_t* a, const uint32_t* b) {
    asm volatile(
        "mma.sync.aligned.m16n8k16.row.col.f32.f16.f16.f32 "
        "{%0,%1,%2,%3}, {%4,%5,%6,%7}, {%8,%9}, {%0,%1,%2,%3};"
        : "+f"(c[0]), "+f"(c[1]), "+f"(c[2]), "+f"(c[3])
        : "r"(a[0]), "r"(a[1]), "r"(a[2]), "r"(a[3]), "r"(b[0]), "r"(b[1]));
}

// XOR swizzle inside a 128-row x 64B tile: (row, c16 in 0..3) -> byte offset
__device__ __forceinline__ uint32_t sw_off(int row, int c16) {
    return (uint32_t)(row * 64 + ((c16 ^ ((row >> 1) & 3)) << 4));
}

// ---------------- setup: discretize in fp64, build W1 and W2 (merged) --------
__global__ void setup_kernel(const float* __restrict__ Lre, const float* __restrict__ Lim,
                             const float* __restrict__ Bre, const float* __restrict__ Bim,
                             const float* __restrict__ Cre, const float* __restrict__ Cim,
                             const float* __restrict__ log_step) {
    if (blockIdx.x >= PP) {
        int idx = (blockIdx.x - PP) * blockDim.x + threadIdx.x;
        int h = idx >> 9, p = idx & (PP - 1);
        d_W2[h * K2 + p]      = __float2half( 2.0f * Cre[h * PP + p]);
        d_W2[h * K2 + PP + p] = __float2half(-2.0f * Cim[h * PP + p]);
        return;
    }
    int p = blockIdx.x;
    __shared__ float2 s_f;
    if (threadIdx.x == 0) {
        double lr = (double)Lre[p], li = (double)Lim[p];
        double dt = exp((double)log_step[p]);
        double mag = exp(lr * dt);
        double lam_r = mag * cos(li * dt);
        double lam_i = mag * sin(li * dt);
        d_Lam[p] = make_float2((float)lam_r, (float)lam_i);
        double nr = lam_r - 1.0, ni = lam_i;
        double den = lr * lr + li * li;
        s_f = make_float2((float)((nr * lr + ni * li) / den),
                          (float)((ni * lr - nr * li) / den));
        // lam^32 via 5 squarings (double)
        double pr = lam_r, pi = lam_i;
        #pragma unroll
        for (int i = 0; i < 5; i++) { double r2 = pr*pr - pi*pi, i2 = 2.0*pr*pi; pr = r2; pi = i2; }
        d_LamPow[p] = make_float2((float)pr, (float)pi);
    }
    __syncthreads();
    float fr = s_f.x, fi = s_f.y;
    for (int h = threadIdx.x; h < HH; h += blockDim.x) {
        float br = Bre[p * HH + h], bi = Bim[p * HH + h];
        d_W1[p * K1 + h]        = __float2half(fr * br - fi * bi);   // Re(B_bar)
        d_W1[(PP + p) * K1 + h] = __float2half(fr * bi + fi * br);   // Im(B_bar)
    }
}

// vectorized: 8 floats -> 8 halves (one uint4 store) per thread
__global__ void uconv_kernel(const float* __restrict__ u, __half* __restrict__ dst) {
    size_t i = ((size_t)blockIdx.x * blockDim.x + threadIdx.x) * 8;
    float4 a = *(const float4*)(u + i);
    float4 b = *(const float4*)(u + i + 4);
    __half2 h0 = __floats2half2_rn(a.x, a.y);
    __half2 h1 = __floats2half2_rn(a.z, a.w);
    __half2 h2 = __floats2half2_rn(b.x, b.y);
    __half2 h3 = __floats2half2_rn(b.z, b.w);
    uint4 out;
    out.x = *(uint32_t*)&h0; out.y = *(uint32_t*)&h1;
    out.z = *(uint32_t*)&h2; out.w = *(uint32_t*)&h3;
    *(uint4*)(dst + i) = out;
}

// ---------------- HMMA fp16 GEMM: C[m,n] = sum_k A[m,k]*W[n,k] ---------------
// 128x128 CTA tile, BK=32, 4 warps of 64x64 (128 threads).
// 4-stage cp.async pipeline, 64B-row XOR-swizzled tiles, 1 barrier/chunk.
#define TILE_B  (128 * 64)               // 8192 B
#define STAGE_B (2 * TILE_B)             // A, W = 16384 B
#define NSTAGE  4
#define GSMEM   (NSTAGE * STAGE_B)       // 65536 B

template <int OUT_HALF>
__global__ void __launch_bounds__(128, 2)
hmma_gemm(const __half* __restrict__ A, const __half* __restrict__ W,
          void* __restrict__ Cv, int N, int K) {
    extern __shared__ char smem[];
    const uint32_t sb = smem_u32(smem);
    const int tid = threadIdx.x;
    const int wid = tid >> 5, lane = tid & 31;
    const int wm = wid >> 1, wn = wid & 1;       // warp tile: rows wm*64, cols wn*64
    const int m0 = blockIdx.y * 128, n0 = blockIdx.x * 128;

    const char* srcs[2] = {
        (const char*)(A + (size_t)m0 * K),
        (const char*)(W + (size_t)n0 * K) };
    const size_t rstride = (size_t)K * 2;

    auto prefetch = [&](int stage, int ci) {
        #pragma unroll
        for (int it = 0; it < 8; it++) {
            int id = it * 128 + tid;            // 0..1023
            int t = id >> 9;                    // tile 0..1
            int w = id & 511;
            int row = w >> 2, c = w & 3;
            cp16(sb + stage * STAGE_B + t * TILE_B + sw_off(row, c),
                 srcs[t] + (size_t)ci * 64 + (size_t)row * rstride + c * 16);
        }
    };

    float acc[4][8][4];
    #pragma unroll
    for (int i = 0; i < 4; i++)
        #pragma unroll
        for (int j = 0; j < 8; j++)
            #pragma unroll
            for (int q = 0; q < 4; q++) acc[i][j][q] = 0.f;

    const int nch = K / 32;
    prefetch(0, 0); CP_COMMIT();
    prefetch(1, 1); CP_COMMIT();
    prefetch(2, 2); CP_COMMIT();

    // fragment address components (per lane)
    const int a_row = lane & 15;
    const int a_c   = lane >> 4;                  // +0 or +1 16B column
    const int b_row = (lane & 7) + ((lane >> 4) & 1) * 8;
    const int b_c   = (lane >> 3) & 1;

    int s = 0;
    for (int ci = 0; ci < nch; ci++) {
        CP_WAIT(2);
        __syncthreads();

        uint32_t sA = sb + s * STAGE_B + 0 * TILE_B;
        uint32_t sW = sb + s * STAGE_B + 1 * TILE_B;

        #pragma unroll
        for (int ks = 0; ks < 2; ks++) {
            // B fragments up front
            uint32_t bw[8][2];
            #pragma unroll
            for (int np = 0; np < 4; np++) {
                int brow = wn * 64 + np * 16 + b_row;
                uint32_t r[4];
                ldm_x4(sW + sw_off(brow, ks * 2 + b_c), r);
                bw[np*2][0] = r[0]; bw[np*2][1] = r[1];
                bw[np*2+1][0] = r[2]; bw[np*2+1][1] = r[3];
            }
            // A-fragment lookahead: double-buffered in registers
            uint32_t av[2][4];
            ldm_x4(sA + sw_off(wm * 64 + a_row, ks * 2 + a_c), av[0]);
            #pragma unroll
            for (int mt = 0; mt < 4; mt++) {
                if (mt < 3) {
                    int arow = wm * 64 + (mt + 1) * 16 + a_row;
                    ldm_x4(sA + sw_off(arow, ks * 2 + a_c), av[(mt + 1) & 1]);
                }
                #pragma unroll
                for (int nt = 0; nt < 8; nt++) hmma(acc[mt][nt], av[mt & 1], bw[nt]);
            }
        }
        // prefetch 3 chunks ahead into the stage freed by this iteration
        if (ci + 3 < nch) prefetch((s + 3) & 3, ci + 3);
        CP_COMMIT();
        s = (s + 1) & 3;
    }

    // epilogue
    #pragma unroll
    for (int mt = 0; mt < 4; mt++) {
        int r = m0 + wm * 64 + mt * 16 + (lane >> 2);
        #pragma unroll
        for (int nt = 0; nt < 8; nt++) {
            int c = n0 + wn * 64 + nt * 8 + (lane & 3) * 2;
            if (OUT_HALF) {
                __half* C = (__half*)Cv;
                *(__half2*)(C + (size_t)r * N + c) =
                    __floats2half2_rn(acc[mt][nt][0], acc[mt][nt][1]);
                *(__half2*)(C + (size_t)(r + 8) * N + c) =
                    __floats2half2_rn(acc[mt][nt][2], acc[mt][nt][3]);
            } else {
                float* C = (float*)Cv;
                *(float2*)(C + (size_t)r * N + c)       = make_float2(acc[mt][nt][0], acc[mt][nt][1]);
                *(float2*)(C + (size_t)(r + 8) * N + c) = make_float2(acc[mt][nt][2], acc[mt][nt][3]);
            }
        }
    }
}

// ---------------- chunked complex scan over L (half-pipeline, BH batches) ----
__global__ void scan_phaseA(const __half* __restrict__ Bu, float2* __restrict__ yend) {
    int idx = blockIdx.x * blockDim.x + threadIdx.x;   // 0 .. BH*NCHUNK*128-1
    int pv = idx & 127;                  // 4-half group; p0 = 4*pv
    int c  = (idx >> 7) & (NCHUNK - 1);
    int b  = idx >> 14;                  // 0..BH-1
    float2 lam[4];
    float xr[4], xi[4];
    #pragma unroll
    for (int q = 0; q < 4; q++) { lam[q] = d_Lam[4 * pv + q]; xr[q] = 0.f; xi[q] = 0.f; }
    size_t base = ((size_t)b * LL + (size_t)c * CLEN) * N1;
    const uint2* Xr = (const uint2*)(Bu + base) + pv;
    const uint2* Xi = (const uint2*)(Bu + base + PP) + pv;
    #pragma unroll 4
    for (int j = 0; j < CLEN; j++) {
        uint2 vr = Xr[(size_t)j * (N1 / 4)];
        uint2 vi = Xi[(size_t)j * (N1 / 4)];
        float2 br01 = __half22float2(*(__half2*)&vr.x);
        float2 br23 = __half22float2(*(__half2*)&vr.y);
        float2 bi01 = __half22float2(*(__half2*)&vi.x);
        float2 bi23 = __half22float2(*(__half2*)&vi.y);
        float br[4] = {br01.x, br01.y, br23.x, br23.y};
        float bi[4] = {bi01.x, bi01.y, bi23.x, bi23.y};
        #pragma unroll
        for (int q = 0; q < 4; q++) {
            float nr = fmaf(lam[q].x, xr[q], fmaf(-lam[q].y, xi[q], br[q]));
            float ni = fmaf(lam[q].x, xi[q], fmaf( lam[q].y, xr[q], bi[q]));
            xr[q] = nr; xi[q] = ni;
        }
    }
    int yb = (b * NCHUNK + c) * PP + 4 * pv;
    #pragma unroll
    for (int q = 0; q < 4; q++) yend[yb + q] = make_float2(xr[q], xi[q]);
}

__global__ void scan_phaseB(const float2* __restrict__ yend, float2* __restrict__ cin) {
    int idx = blockIdx.x * blockDim.x + threadIdx.x;   // 0 .. BH*PP-1
    int p = idx & (PP - 1);
    int b = idx >> 9;
    float2 pw = d_LamPow[p];
    float cr = 0.f, ci = 0.f;
    #pragma unroll 8
    for (int c = 0; c < NCHUNK; c++) {
        cin[(b * NCHUNK + c) * PP + p] = make_float2(cr, ci);
        float2 ye = yend[(b * NCHUNK + c) * PP + p];
        float nr = fmaf(pw.x, cr, fmaf(-pw.y, ci, ye.x));
        float ni = fmaf(pw.x, ci, fmaf( pw.y, cr, ye.y));
        cr = nr; ci = ni;
    }
}

// phaseC: apply carry-in, emit xs rounded to fp16 for GEMM2
__global__ void scan_phaseC(const __half* __restrict__ Bu, const float2* __restrict__ cin,
                            __half* __restrict__ Xh) {
    int idx = blockIdx.x * blockDim.x + threadIdx.x;
    int pv = idx & 127;
    int c  = (idx >> 7) & (NCHUNK - 1);
    int b  = idx >> 14;
    float2 lam[4];
    float xr[4], xi[4];
    int cb = (b * NCHUNK + c) * PP + 4 * pv;
    #pragma unroll
    for (int q = 0; q < 4; q++) {
        lam[q] = d_Lam[4 * pv + q];
        float2 c0 = cin[cb + q];
        xr[q] = c0.x; xi[q] = c0.y;
    }
    size_t mrow = (size_t)b * LL + (size_t)c * CLEN;
    const uint2* Xr = (const uint2*)(Bu + mrow * N1) + pv;
    const uint2* Xi = (const uint2*)(Bu + mrow * N1 + PP) + pv;
    uint2* Hr = (uint2*)(Xh + mrow * K2) + pv;
    uint2* Hi = (uint2*)(Xh + mrow * K2 + PP) + pv;
    #pragma unroll 4
    for (int j = 0; j < CLEN; j++) {
        uint2 vr = Xr[(size_t)j * (N1 / 4)];
        uint2 vi = Xi[(size_t)j * (N1 / 4)];
        float2 br01 = __half22float2(*(__half2*)&vr.x);
        float2 br23 = __half22float2(*(__half2*)&vr.y);
        float2 bi01 = __half22float2(*(__half2*)&vi.x);
        float2 bi23 = __half22float2(*(__half2*)&vi.y);
        float br[4] = {br01.x, br01.y, br23.x, br23.y};
        float bi[4] = {bi01.x, bi01.y, bi23.x, bi23.y};
        #pragma unroll
        for (int q = 0; q < 4; q++) {
            float nr = fmaf(lam[q].x, xr[q], fmaf(-lam[q].y, xi[q], br[q]));
            float ni = fmaf(lam[q].x, xi[q], fmaf( lam[q].y, xr[q], bi[q]));
            xr[q] = nr; xi[q] = ni;
        }
        __half2 hr01 = __floats2half2_rn(xr[0], xr[1]);
        __half2 hr23 = __floats2half2_rn(xr[2], xr[3]);
        __half2 hi01 = __floats2half2_rn(xi[0], xi[1]);
        __half2 hi23 = __floats2half2_rn(xi[2], xi[3]);
        uint2 wr, wi;
        wr.x = *(uint32_t*)&hr01; wr.y = *(uint32_t*)&hr23;
        wi.x = *(uint32_t*)&hi01; wi.y = *(uint32_t*)&hi23;
        Hr[(size_t)j * (K2 / 4)] = wr;
        Hi[(size_t)j * (K2 / 4)] = wi;
    }
}

// ---------------- launch: two independent half-pipelines on two streams ------
extern "C" void kernel_launch(void* const* d_in, const int* in_sizes, int n_in,
                              void* d_out, int out_size) {
    const float* Lre      = (const float*)d_in[0];
    const float* Lim      = (const float*)d_in[1];
    const float* Bre      = (const float*)d_in[2];
    const float* Bim      = (const float*)d_in[3];
    const float* Cre      = (const float*)d_in[4];
    const float* Cim      = (const float*)d_in[5];
    const float* log_step = (const float*)d_in[6];
    const float* u        = (const float*)d_in[7];
    float* out = (float*)d_out;

    __half *Bu, *Uh, *Xh, *W1p, *W2p;
    float2 *yend, *cin;
    cudaGetSymbolAddress((void**)&Bu,   d_Bu);
    cudaGetSymbolAddress((void**)&Uh,   d_Uh);
    cudaGetSymbolAddress((void**)&Xh,   d_Xh);
    cudaGetSymbolAddress((void**)&W1p,  d_W1);
    cudaGetSymbolAddress((void**)&W2p,  d_W2);
    cudaGetSymbolAddress((void**)&yend, d_yend);
    cudaGetSymbolAddress((void**)&cin,  d_cin);

    cudaFuncSetAttribute(hmma_gemm<1>, cudaFuncAttributeMaxDynamicSharedMemorySize, GSMEM);
    cudaFuncSetAttribute(hmma_gemm<0>, cudaFuncAttributeMaxDynamicSharedMemorySize, GSMEM);

    cudaStream_t s0 = 0, s1;
    cudaStreamCreateWithFlags(&s1, cudaStreamNonBlocking);
    cudaEvent_t evSetup, evJoin;
    cudaEventCreateWithFlags(&evSetup, cudaEventDisableTiming);
    cudaEventCreateWithFlags(&evJoin,  cudaEventDisableTiming);

    // shared setup on s0, then fork s1
    setup_kernel<<<PP + (HH * PP) / 256, 256, 0, s0>>>(Lre, Lim, Bre, Bim, Cre, Cim, log_step);
    cudaEventRecord(evSetup, s0);
    cudaStreamWaitEvent(s1, evSetup, 0);

    const int UCONV_BLKS = (int)(((size_t)MH * K1) / 8 / 256);
    const int SCAN_BLKS  = (BH * NCHUNK * PP / 4) / 256;
    const int SB_BLKS    = (BH * PP) / 256;

    for (int h = 0; h < 2; h++) {
        cudaStream_t st = h ? s1 : s0;
        size_t tok = (size_t)h * MH;                 // token offset
        const float* u_h  = u  + tok * HH;
        __half* Uh_h = Uh + tok * K1;
        __half* Bu_h = Bu + tok * N1;
        __half* Xh_h = Xh + tok * K2;
        float* out_h = out + tok * N2;
        float2* ye_h = yend + (size_t)h * BH * NCHUNK * PP;
        float2* ci_h = cin  + (size_t)h * BH * NCHUNK * PP;

        uconv_kernel<<<UCONV_BLKS, 256, 0, st>>>(u_h, Uh_h);
        hmma_gemm<1><<<dim3(N1 / 128, MH / 128), 128, GSMEM, st>>>(Uh_h, W1p, Bu_h, N1, K1);
        scan_phaseA<<<SCAN_BLKS, 256, 0, st>>>(Bu_h, ye_h);
        scan_phaseB<<<SB_BLKS, 256, 0, st>>>(ye_h, ci_h);
        scan_phaseC<<<SCAN_BLKS, 256, 0, st>>>(Bu_h, ci_h, Xh_h);
        hmma_gemm<0><<<dim3(N2 / 128, MH / 128), 128, GSMEM, st>>>(Xh_h, W2p, out_h, N2, K2);
    }

    // join s1 back into s0 before returning (required for capture)
    cudaEventRecord(evJoin, s1);
    cudaStreamWaitEvent(s0, evJoin, 0);

    cudaEventDestroy(evSetup);
    cudaEventDestroy(evJoin);
    cudaStreamDestroy(s1);
}

// round 17
// speedup vs baseline: 1.2130x; 1.0201x over previous
#include <cuda_runtime.h>
#include <cuda_fp16.h>
#include <math.h>
#include <stdint.h>

// Problem constants
#define BB    8
#define NQ    4           // number of parallel pipelines (quarters)
#define BQ    2           // batches per quarter
#define LL    4096
#define HH    512
#define PP    512
#define MM    (BB*LL)     // 32768 tokens
#define MQ    (BQ*LL)     // 8192 tokens per quarter
#define N1    (2*PP)      // 1024  (Bu_re | Bu_im)
#define K1    HH          // 512
#define N2    HH          // 512
#define K2    (2*PP)      // 1024  (x_re | x_im)
#define NCHUNK 128
#define CLEN   32         // LL / NCHUNK

// ---------------- static device scratch -------------------------------------
__device__ __half  d_Bu [(size_t)MM * N1];   // Bu fp16 (64MB)
__device__ __half  d_Uh [(size_t)MM * K1];   // u rounded to fp16 (32MB)
__device__ __half  d_Xh [(size_t)MM * K2];   // xs rounded to fp16 (64MB)
__device__ __half  d_W1 [N1 * K1];           // B_bar folded, fp16
__device__ __half  d_W2 [N2 * K2];           // [2C_re | -2C_im], fp16
__device__ float2 d_Lam[PP];
__device__ float2 d_LamPow[PP];              // lam^CLEN
__device__ float2 d_yend[BB * NCHUNK * PP];
__device__ float2 d_cin [BB * NCHUNK * PP];

// ---------------- helpers ----------------------------------------------------
__device__ __forceinline__ uint32_t smem_u32(const void* p) {
    uint32_t a;
    asm("{ .reg .u64 t; cvta.to.shared.u64 t, %1; cvt.u32.u64 %0, t; }" : "=r"(a) : "l"(p));
    return a;
}
__device__ __forceinline__ void cp16(uint32_t saddr, const void* g) {
    asm volatile("cp.async.cg.shared.global [%0], [%1], 16;" :: "r"(saddr), "l"(g));
}
#define CP_COMMIT() asm volatile("cp.async.commit_group;" ::: "memory")
#define CP_WAIT(n)  asm volatile("cp.async.wait_group %0;" :: "n"(n) : "memory")

__device__ __forceinline__ void ldm_x4(uint32_t addr, uint32_t* r) {
    asm volatile("ldmatrix.sync.aligned.m8n8.x4.shared.b16 {%0,%1,%2,%3}, [%4];"
                 : "=r"(r[0]), "=r"(r[1]), "=r"(r[2]), "=r"(r[3]) : "r"(addr));
}
__device__ __forceinline__ void hmma(float* c, const uint32_t* a, const uint32_t* b) {
    asm volatile(
        "mma.sync.aligned.m16n8k16.row.col.f32.f16.f16.f32 "
        "{%0,%1,%2,%3}, {%4,%5,%6,%7}, {%8,%9}, {%0,%1,%2,%3};"
        : "+f"(c[0]), "+f"(c[1]), "+f"(c[2]), "+f"(c[3])
        : "r"(a[0]), "r"(a[1]), "r"(a[2]), "r"(a[3]), "r"(b[0]), "r"(b[1]));
}

// XOR swizzle inside a 128-row x 64B tile: (row, c16 in 0..3) -> byte offset
__device__ __forceinline__ uint32_t sw_off(int row, int c16) {
    return (uint32_t)(row * 64 + ((c16 ^ ((row >> 1) & 3)) << 4));
}

// ---------------- setup: discretize in fp64, build W1 and W2 (merged) --------
__global__ void setup_kernel(const float* __restrict__ Lre, const float* __restrict__ Lim,
                             const float* __restrict__ Bre, const float* __restrict__ Bim,
                             const float* __restrict__ Cre, const float* __restrict__ Cim,
                             const float* __restrict__ log_step) {
    if (blockIdx.x >= PP) {
        int idx = (blockIdx.x - PP) * blockDim.x + threadIdx.x;
        int h = idx >> 9, p = idx & (PP - 1);
        d_W2[h * K2 + p]      = __float2half( 2.0f * Cre[h * PP + p]);
        d_W2[h * K2 + PP + p] = __float2half(-2.0f * Cim[h * PP + p]);
        return;
    }
    int p = blockIdx.x;
    __shared__ float2 s_f;
    if (threadIdx.x == 0) {
        double lr = (double)Lre[p], li = (double)Lim[p];
        double dt = exp((double)log_step[p]);
        double mag = exp(lr * dt);
        double lam_r = mag * cos(li * dt);
        double lam_i = mag * sin(li * dt);
        d_Lam[p] = make_float2((float)lam_r, (float)lam_i);
        double nr = lam_r - 1.0, ni = lam_i;
        double den = lr * lr + li * li;
        s_f = make_float2((float)((nr * lr + ni * li) / den),
                          (float)((ni * lr - nr * li) / den));
        // lam^32 via 5 squarings (double)
        double pr = lam_r, pi = lam_i;
        #pragma unroll
        for (int i = 0; i < 5; i++) { double r2 = pr*pr - pi*pi, i2 = 2.0*pr*pi; pr = r2; pi = i2; }
        d_LamPow[p] = make_float2((float)pr, (float)pi);
    }
    __syncthreads();
    float fr = s_f.x, fi = s_f.y;
    for (int h = threadIdx.x; h < HH; h += blockDim.x) {
        float br = Bre[p * HH + h], bi = Bim[p * HH + h];
        d_W1[p * K1 + h]        = __float2half(fr * br - fi * bi);   // Re(B_bar)
        d_W1[(PP + p) * K1 + h] = __float2half(fr * bi + fi * br);   // Im(B_bar)
    }
}

// vectorized: 8 floats -> 8 halves (one uint4 store) per thread
__global__ void uconv_kernel(const float* __restrict__ u, __half* __restrict__ dst) {
    size_t i = ((size_t)blockIdx.x * blockDim.x + threadIdx.x) * 8;
    float4 a = *(const float4*)(u + i);
    float4 b = *(const float4*)(u + i + 4);
    __half2 h0 = __floats2half2_rn(a.x, a.y);
    __half2 h1 = __floats2half2_rn(a.z, a.w);
    __half2 h2 = __floats2half2_rn(b.x, b.y);
    __half2 h3 = __floats2half2_rn(b.z, b.w);
    uint4 out;
    out.x = *(uint32_t*)&h0; out.y = *(uint32_t*)&h1;
    out.z = *(uint32_t*)&h2; out.w = *(uint32_t*)&h3;
    *(uint4*)(dst + i) = out;
}

// ---------------- HMMA fp16 GEMM: C[m,n] = sum_k A[m,k]*W[n,k] ---------------
// 128x128 CTA tile, BK=32, 4 warps of 64x64 (128 threads).
// 4-stage cp.async pipeline, 64B-row XOR-swizzled tiles, 1 barrier/chunk.
#define TILE_B  (128 * 64)               // 8192 B
#define STAGE_B (2 * TILE_B)             // A, W = 16384 B
#define NSTAGE  4
#define GSMEM   (NSTAGE * STAGE_B)       // 65536 B

template <int OUT_HALF>
__global__ void __launch_bounds__(128, 2)
hmma_gemm(const __half* __restrict__ A, const __half* __restrict__ W,
          void* __restrict__ Cv, int N, int K) {
    extern __shared__ char smem[];
    const uint32_t sb = smem_u32(smem);
    const int tid = threadIdx.x;
    const int wid = tid >> 5, lane = tid & 31;
    const int wm = wid >> 1, wn = wid & 1;       // warp tile: rows wm*64, cols wn*64
    const int m0 = blockIdx.y * 128, n0 = blockIdx.x * 128;

    const char* srcs[2] = {
        (const char*)(A + (size_t)m0 * K),
        (const char*)(W + (size_t)n0 * K) };
    const size_t rstride = (size_t)K * 2;

    auto prefetch = [&](int stage, int ci) {
        #pragma unroll
        for (int it = 0; it < 8; it++) {
            int id = it * 128 + tid;            // 0..1023
            int t = id >> 9;                    // tile 0..1
            int w = id & 511;
            int row = w >> 2, c = w & 3;
            cp16(sb + stage * STAGE_B + t * TILE_B + sw_off(row, c),
                 srcs[t] + (size_t)ci * 64 + (size_t)row * rstride + c * 16);
        }
    };

    float acc[4][8][4];
    #pragma unroll
    for (int i = 0; i < 4; i++)
        #pragma unroll
        for (int j = 0; j < 8; j++)
            #pragma unroll
            for (int q = 0; q < 4; q++) acc[i][j][q] = 0.f;

    const int nch = K / 32;
    prefetch(0, 0); CP_COMMIT();
    prefetch(1, 1); CP_COMMIT();
    prefetch(2, 2); CP_COMMIT();

    // fragment address components (per lane)
    const int a_row = lane & 15;
    const int a_c   = lane >> 4;                  // +0 or +1 16B column
    const int b_row = (lane & 7) + ((lane >> 4) & 1) * 8;
    const int b_c   = (lane >> 3) & 1;

    int s = 0;
    for (int ci = 0; ci < nch; ci++) {
        CP_WAIT(2);
        __syncthreads();

        uint32_t sA = sb + s * STAGE_B + 0 * TILE_B;
        uint32_t sW = sb + s * STAGE_B + 1 * TILE_B;

        #pragma unroll
        for (int ks = 0; ks < 2; ks++) {
            // B fragments up front
            uint32_t bw[8][2];
            #pragma unroll
            for (int np = 0; np < 4; np++) {
                int brow = wn * 64 + np * 16 + b_row;
                uint32_t r[4];
                ldm_x4(sW + sw_off(brow, ks * 2 + b_c), r);
                bw[np*2][0] = r[0]; bw[np*2][1] = r[1];
                bw[np*2+1][0] = r[2]; bw[np*2+1][1] = r[3];
            }
            // A-fragment lookahead: double-buffered in registers
            uint32_t av[2][4];
            ldm_x4(sA + sw_off(wm * 64 + a_row, ks * 2 + a_c), av[0]);
            #pragma unroll
            for (int mt = 0; mt < 4; mt++) {
                if (mt < 3) {
                    int arow = wm * 64 + (mt + 1) * 16 + a_row;
                    ldm_x4(sA + sw_off(arow, ks * 2 + a_c), av[(mt + 1) & 1]);
                }
                #pragma unroll
                for (int nt = 0; nt < 8; nt++) hmma(acc[mt][nt], av[mt & 1], bw[nt]);
            }
        }
        // prefetch 3 chunks ahead into the stage freed by this iteration
        if (ci + 3 < nch) prefetch((s + 3) & 3, ci + 3);
        CP_COMMIT();
        s = (s + 1) & 3;
    }

    // epilogue
    #pragma unroll
    for (int mt = 0; mt < 4; mt++) {
        int r = m0 + wm * 64 + mt * 16 + (lane >> 2);
        #pragma unroll
        for (int nt = 0; nt < 8; nt++) {
            int c = n0 + wn * 64 + nt * 8 + (lane & 3) * 2;
            if (OUT_HALF) {
                __half* C = (__half*)Cv;
                *(__half2*)(C + (size_t)r * N + c) =
                    __floats2half2_rn(acc[mt][nt][0], acc[mt][nt][1]);
                *(__half2*)(C + (size_t)(r + 8) * N + c) =
                    __floats2half2_rn(acc[mt][nt][2], acc[mt][nt][3]);
            } else {
                float* C = (float*)Cv;
                *(float2*)(C + (size_t)r * N + c)       = make_float2(acc[mt][nt][0], acc[mt][nt][1]);
                *(float2*)(C + (size_t)(r + 8) * N + c) = make_float2(acc[mt][nt][2], acc[mt][nt][3]);
            }
        }
    }
}

// ---------------- chunked complex scan over L (per-quarter, BQ batches) ------
__global__ void scan_phaseA(const __half* __restrict__ Bu, float2* __restrict__ yend) {
    int idx = blockIdx.x * blockDim.x + threadIdx.x;   // 0 .. BQ*NCHUNK*128-1
    int pv = idx & 127;                  // 4-half group; p0 = 4*pv
    int c  = (idx >> 7) & (NCHUNK - 1);
    int b  = idx >> 14;                  // 0..BQ-1
    float2 lam[4];
    float xr[4], xi[4];
    #pragma unroll
    for (int q = 0; q < 4; q++) { lam[q] = d_Lam[4 * pv + q]; xr[q] = 0.f; xi[q] = 0.f; }
    size_t base = ((size_t)b * LL + (size_t)c * CLEN) * N1;
    const uint2* Xr = (const uint2*)(Bu + base) + pv;
    const uint2* Xi = (const uint2*)(Bu + base + PP) + pv;
    #pragma unroll 4
    for (int j = 0; j < CLEN; j++) {
        uint2 vr = Xr[(size_t)j * (N1 / 4)];
        uint2 vi = Xi[(size_t)j * (N1 / 4)];
        float2 br01 = __half22float2(*(__half2*)&vr.x);
        float2 br23 = __half22float2(*(__half2*)&vr.y);
        float2 bi01 = __half22float2(*(__half2*)&vi.x);
        float2 bi23 = __half22float2(*(__half2*)&vi.y);
        float br[4] = {br01.x, br01.y, br23.x, br23.y};
        float bi[4] = {bi01.x, bi01.y, bi23.x, bi23.y};
        #pragma unroll
        for (int q = 0; q < 4; q++) {
            float nr = fmaf(lam[q].x, xr[q], fmaf(-lam[q].y, xi[q], br[q]));
            float ni = fmaf(lam[q].x, xi[q], fmaf( lam[q].y, xr[q], bi[q]));
            xr[q] = nr; xi[q] = ni;
        }
    }
    int yb = (b * NCHUNK + c) * PP + 4 * pv;
    #pragma unroll
    for (int q = 0; q < 4; q++) yend[yb + q] = make_float2(xr[q], xi[q]);
}

__global__ void scan_phaseB(const float2* __restrict__ yend, float2* __restrict__ cin) {
    int idx = blockIdx.x * blockDim.x + threadIdx.x;   // 0 .. BQ*PP-1
    int p = idx & (PP - 1);
    int b = idx >> 9;
    float2 pw = d_LamPow[p];
    float cr = 0.f, ci = 0.f;
    #pragma unroll 8
    for (int c = 0; c < NCHUNK; c++) {
        cin[(b * NCHUNK + c) * PP + p] = make_float2(cr, ci);
        float2 ye = yend[(b * NCHUNK + c) * PP + p];
        float nr = fmaf(pw.x, cr, fmaf(-pw.y, ci, ye.x));
        float ni = fmaf(pw.x, ci, fmaf( pw.y, cr, ye.y));
        cr = nr; ci = ni;
    }
}

// phaseC: apply carry-in, emit xs rounded to fp16 for GEMM2
__global__ void scan_phaseC(const __half* __restrict__ Bu, const float2* __restrict__ cin,
                            __half* __restrict__ Xh) {
    int idx = blockIdx.x * blockDim.x + threadIdx.x;
    int pv = idx & 127;
    int c  = (idx >> 7) & (NCHUNK - 1);
    int b  = idx >> 14;
    float2 lam[4];
    float xr[4], xi[4];
    int cb = (b * NCHUNK + c) * PP + 4 * pv;
    #pragma unroll
    for (int q = 0; q < 4; q++) {
        lam[q] = d_Lam[4 * pv + q];
        float2 c0 = cin[cb + q];
        xr[q] = c0.x; xi[q] = c0.y;
    }
    size_t mrow = (size_t)b * LL + (size_t)c * CLEN;
    const uint2* Xr = (const uint2*)(Bu + mrow * N1) + pv;
    const uint2* Xi = (const uint2*)(Bu + mrow * N1 + PP) + pv;
    uint2* Hr = (uint2*)(Xh + mrow * K2) + pv;
    uint2* Hi = (uint2*)(Xh + mrow * K2 + PP) + pv;
    #pragma unroll 4
    for (int j = 0; j < CLEN; j++) {
        uint2 vr = Xr[(size_t)j * (N1 / 4)];
        uint2 vi = Xi[(size_t)j * (N1 / 4)];
        float2 br01 = __half22float2(*(__half2*)&vr.x);
        float2 br23 = __half22float2(*(__half2*)&vr.y);
        float2 bi01 = __half22float2(*(__half2*)&vi.x);
        float2 bi23 = __half22float2(*(__half2*)&vi.y);
        float br[4] = {br01.x, br01.y, br23.x, br23.y};
        float bi[4] = {bi01.x, bi01.y, bi23.x, bi23.y};
        #pragma unroll
        for (int q = 0; q < 4; q++) {
            float nr = fmaf(lam[q].x, xr[q], fmaf(-lam[q].y, xi[q], br[q]));
            float ni = fmaf(lam[q].x, xi[q], fmaf( lam[q].y, xr[q], bi[q]));
            xr[q] = nr; xi[q] = ni;
        }
        __half2 hr01 = __floats2half2_rn(xr[0], xr[1]);
        __half2 hr23 = __floats2half2_rn(xr[2], xr[3]);
        __half2 hi01 = __floats2half2_rn(xi[0], xi[1]);
        __half2 hi23 = __floats2half2_rn(xi[2], xi[3]);
        uint2 wr, wi;
        wr.x = *(uint32_t*)&hr01; wr.y = *(uint32_t*)&hr23;
        wi.x = *(uint32_t*)&hi01; wi.y = *(uint32_t*)&hi23;
        Hr[(size_t)j * (K2 / 4)] = wr;
        Hi[(size_t)j * (K2 / 4)] = wi;
    }
}

// ---------------- launch: 4 independent quarter-pipelines on 4 streams -------
extern "C" void kernel_launch(void* const* d_in, const int* in_sizes, int n_in,
                              void* d_out, int out_size) {
    const float* Lre      = (const float*)d_in[0];
    const float* Lim      = (const float*)d_in[1];
    const float* Bre      = (const float*)d_in[2];
    const float* Bim      = (const float*)d_in[3];
    const float* Cre      = (const float*)d_in[4];
    const float* Cim      = (const float*)d_in[5];
    const float* log_step = (const float*)d_in[6];
    const float* u        = (const float*)d_in[7];
    float* out = (float*)d_out;

    __half *Bu, *Uh, *Xh, *W1p, *W2p;
    float2 *yend, *cin;
    cudaGetSymbolAddress((void**)&Bu,   d_Bu);
    cudaGetSymbolAddress((void**)&Uh,   d_Uh);
    cudaGetSymbolAddress((void**)&Xh,   d_Xh);
    cudaGetSymbolAddress((void**)&W1p,  d_W1);
    cudaGetSymbolAddress((void**)&W2p,  d_W2);
    cudaGetSymbolAddress((void**)&yend, d_yend);
    cudaGetSymbolAddress((void**)&cin,  d_cin);

    cudaFuncSetAttribute(hmma_gemm<1>, cudaFuncAttributeMaxDynamicSharedMemorySize, GSMEM);
    cudaFuncSetAttribute(hmma_gemm<0>, cudaFuncAttributeMaxDynamicSharedMemorySize, GSMEM);

    cudaStream_t st[NQ];
    st[0] = 0;
    for (int q = 1; q < NQ; q++) cudaStreamCreateWithFlags(&st[q], cudaStreamNonBlocking);
    cudaEvent_t evSetup, evJoin[NQ];
    cudaEventCreateWithFlags(&evSetup, cudaEventDisableTiming);
    for (int q = 1; q < NQ; q++) cudaEventCreateWithFlags(&evJoin[q], cudaEventDisableTiming);

    // shared setup on s0, then fork
    setup_kernel<<<PP + (HH * PP) / 256, 256, 0, st[0]>>>(Lre, Lim, Bre, Bim, Cre, Cim, log_step);
    cudaEventRecord(evSetup, st[0]);
    for (int q = 1; q < NQ; q++) cudaStreamWaitEvent(st[q], evSetup, 0);

    const int UCONV_BLKS = (int)(((size_t)MQ * K1) / 8 / 256);
    const int SCAN_BLKS  = (BQ * NCHUNK * PP / 4) / 256;
    const int SB_BLKS    = (BQ * PP) / 256;

    for (int q = 0; q < NQ; q++) {
        size_t tok = (size_t)q * MQ;                 // token offset
        const float* u_q  = u  + tok * HH;
        __half* Uh_q = Uh + tok * K1;
        __half* Bu_q = Bu + tok * N1;
        __half* Xh_q = Xh + tok * K2;
        float* out_q = out + tok * N2;
        float2* ye_q = yend + (size_t)q * BQ * NCHUNK * PP;
        float2* ci_q = cin  + (size_t)q * BQ * NCHUNK * PP;

        uconv_kernel<<<UCONV_BLKS, 256, 0, st[q]>>>(u_q, Uh_q);
        hmma_gemm<1><<<dim3(N1 / 128, MQ / 128), 128, GSMEM, st[q]>>>(Uh_q, W1p, Bu_q, N1, K1);
        scan_phaseA<<<SCAN_BLKS, 256, 0, st[q]>>>(Bu_q, ye_q);
        scan_phaseB<<<SB_BLKS, 256, 0, st[q]>>>(ye_q, ci_q);
        scan_phaseC<<<SCAN_BLKS, 256, 0, st[q]>>>(Bu_q, ci_q, Xh_q);
        hmma_gemm<0><<<dim3(N2 / 128, MQ / 128), 128, GSMEM, st[q]>>>(Xh_q, W2p, out_q, N2, K2);
    }

    // join all side streams back into s0 before returning
    for (int q = 1; q < NQ; q++) {
        cudaEventRecord(evJoin[q], st[q]);
        cudaStreamWaitEvent(st[0], evJoin[q], 0);
    }

    cudaEventDestroy(evSetup);
    for (int q = 1; q < NQ; q++) {
        cudaEventDestroy(evJoin[q]);
        cudaStreamDestroy(st[q]);
    }
}